// round 14
// baseline (speedup 1.0000x reference)
#include <cuda_runtime.h>
#include <cuda_fp16.h>
#include <cstdint>

// ---------------- problem constants ----------------
static constexpr int TOKENS = 4096;
static constexpr int IN_F   = 4096;
static constexpr int OUT_F  = 11008;

static constexpr int BM = 128;
static constexpr int BN = 128;
static constexpr int BK = 64;          // 64 fp16 = 128 bytes per row (SW128 atom row)
static constexpr int STAGES = 3;

static constexpr int M_TILES = TOKENS / BM;   // 32
static constexpr int N_TILES = OUT_F / BN;    // 86
static constexpr int K_TILES = IN_F / BK;     // 64

static constexpr int TILE_BYTES = 128 * BK * 2;     // 16384 (A tile == B tile)
static constexpr int STAGE_BYTES = 2 * TILE_BYTES;  // 32768
static constexpr int SMEM_BYTES = STAGES * STAGE_BYTES; // 98304

static constexpr int X_BLOCKS = M_TILES * K_TILES;  // 2048
static constexpr int W_BLOCKS = N_TILES * K_TILES;  // 5504

// ---------------- device scratch (no cudaMalloc allowed) ----------------
__device__ __align__(1024) uint8_t g_xbuf[(size_t)M_TILES * K_TILES * TILE_BYTES]; // 32 MB fp16 tiles, SW128
__device__ __align__(1024) uint8_t g_wbuf[(size_t)N_TILES * K_TILES * TILE_BYTES]; // 88 MB fp16 tiles, SW128

// ---------------- helpers ----------------
__device__ __forceinline__ uint32_t smem_u32(const void* p) {
    uint32_t a;
    asm("{ .reg .u64 t; cvta.to.shared.u64 t, %1; cvt.u32.u64 %0, t; }" : "=r"(a) : "l"(p));
    return a;
}
__device__ __forceinline__ uint32_t h2u(__half2 h) { uint32_t u; __builtin_memcpy(&u, &h, 4); return u; }
__device__ __forceinline__ uint32_t swz(uint32_t off) { return off ^ ((off >> 3) & 0x70); }

__device__ __forceinline__ void cpasync16(uint32_t dst, const void* src) {
    asm volatile("cp.async.cg.shared.global [%0], [%1], 16;" :: "r"(dst), "l"(src));
}
__device__ __forceinline__ void cp_commit() { asm volatile("cp.async.commit_group;" ::: "memory"); }
__device__ __forceinline__ void cp_wait1()  { asm volatile("cp.async.wait_group 1;" ::: "memory"); }

__device__ __forceinline__ void ldsm4(uint32_t* r, uint32_t addr) {
    asm volatile("ldmatrix.sync.aligned.m8n8.x4.shared.b16 {%0,%1,%2,%3}, [%4];"
                 : "=r"(r[0]), "=r"(r[1]), "=r"(r[2]), "=r"(r[3]) : "r"(addr) : "memory");
}
__device__ __forceinline__ void mma16816(float* c, const uint32_t* a, const uint32_t* b) {
    asm volatile(
        "mma.sync.aligned.m16n8k16.row.col.f32.f16.f16.f32 "
        "{%0,%1,%2,%3}, {%4,%5,%6,%7}, {%8,%9}, {%0,%1,%2,%3};"
        : "+f"(c[0]), "+f"(c[1]), "+f"(c[2]), "+f"(c[3])
        : "r"(a[0]), "r"(a[1]), "r"(a[2]), "r"(a[3]), "r"(b[0]), "r"(b[1]));
}

// ---------------- merged prep kernel ----------------
__global__ void prep_kernel(const float* __restrict__ x,
                            const int* __restrict__ wp,
                            const float* __restrict__ scale,
                            const float* __restrict__ zero) {
    const int blk = blockIdx.x;
    const int r = threadIdx.x; // 0..127 = row within tile
    if (blk < X_BLOCKS) {
        const int mt = blk / K_TILES;
        const int kt = blk % K_TILES;
        const float4* src = (const float4*)(x + (size_t)(mt * BM + r) * IN_F + kt * BK);
        uint8_t* dst = g_xbuf + (size_t)blk * TILE_BYTES;
#pragma unroll
        for (int g = 0; g < 8; g++) {
            float4 a = src[2 * g];
            float4 b = src[2 * g + 1];
            uint4 v;
            v.x = h2u(__floats2half2_rn(a.x, a.y));
            v.y = h2u(__floats2half2_rn(a.z, a.w));
            v.z = h2u(__floats2half2_rn(b.x, b.y));
            v.w = h2u(__floats2half2_rn(b.z, b.w));
            uint32_t off = (uint32_t)(r * 128 + g * 16);
            *(uint4*)(dst + swz(off)) = v;
        }
    } else {
        const int wblk = blk - X_BLOCKS;
        const int nt = wblk / K_TILES;
        const int kt = wblk % K_TILES;
        const int row = nt * BN + r;
        const float s = scale[row];
        const float b = -zero[row] * s;
        const uint4* src = (const uint4*)(wp + (size_t)row * (IN_F / 2) + kt * (BK / 2)); // 32 ints
        uint8_t* dst = g_wbuf + (size_t)wblk * TILE_BYTES;
#pragma unroll
        for (int j = 0; j < 8; j++) {
            uint4 q = src[j];
            uint32_t e[4] = {q.x, q.y, q.z, q.w};
            uint32_t h[4];
#pragma unroll
            for (int t = 0; t < 4; t++) {
                float v0 = fmaf((float)(e[t] & 15u), s, b);          // even k
                float v1 = fmaf((float)((e[t] >> 4) & 15u), s, b);   // odd k
                h[t] = h2u(__floats2half2_rn(v0, v1));
            }
            uint4 v = make_uint4(h[0], h[1], h[2], h[3]);
            uint32_t off = (uint32_t)(r * 128 + j * 16);
            *(uint4*)(dst + swz(off)) = v;
        }
    }
}

// ---------------- main GEMM: 512 threads, 16 warps (4x4), warp tile 32x32 ----------------
// 2 CTAs/SM -> 32 warps/SM (8 per SMSP). 3-stage cp.async pipeline.
__global__ void __launch_bounds__(512, 2) gemm_kernel(float* __restrict__ out) {
    extern __shared__ __align__(1024) uint8_t sm[];
    uint32_t sb = smem_u32(sm);
    const int tid  = threadIdx.x;
    const int lane = tid & 31;
    const int warp = tid >> 5;           // 0..15
    const int warp_m = warp & 3;         // 0..3
    const int warp_n = warp >> 2;        // 0..3
    const int mt = blockIdx.x % M_TILES;
    const int nt = blockIdx.x / M_TILES;

    const uint8_t* ag = g_xbuf + (size_t)(mt * K_TILES) * TILE_BYTES;
    const uint8_t* bg = g_wbuf + (size_t)(nt * K_TILES) * TILE_BYTES;

    // cp.async: threads 0..255 load A tile (64 B each), 256..511 load B tile
    const bool isB = tid >= 256;
    const uint32_t cp_off = (uint32_t)(tid & 255) * 64;
    const uint8_t* cp_base = (isB ? bg : ag) + cp_off;
    const uint32_t cp_dst  = (isB ? (uint32_t)TILE_BYTES : 0u) + cp_off;

    // prologue: stages 0 and 1
#pragma unroll
    for (int s = 0; s < 2; s++) {
        uint32_t d = sb + s * STAGE_BYTES + cp_dst;
        const uint8_t* src = cp_base + (size_t)s * TILE_BYTES;
#pragma unroll
        for (int j = 0; j < 4; j++) cpasync16(d + j * 16, src + j * 16);
        cp_commit();
    }

    // per-lane ldmatrix address components (SW128: swz(r*128+c) = r*128 + (c ^ ((r&7)<<4)))
    const int a_row = warp_m * 32 + (lane & 15);          // + 16*mtile
    const uint32_t a_xor = (uint32_t)((a_row & 7) << 4);
    const uint32_t a_cb  = (uint32_t)((lane >> 4) << 4);  // 0 or 16
    const int b_row = warp_n * 32 + (lane & 7) + ((lane >> 4) << 3);  // + 16*p
    const uint32_t b_xor = (uint32_t)((b_row & 7) << 4);
    const uint32_t b_cb  = (uint32_t)((lane & 8) << 1);   // 0 or 16

    const uint32_t aoff0 = (uint32_t)(a_row +  0) * 128;
    const uint32_t aoff1 = (uint32_t)(a_row + 16) * 128;
    const uint32_t boff0 = (uint32_t)(b_row +  0) * 128;
    const uint32_t boff1 = (uint32_t)(b_row + 16) * 128;

    float acc[2][4][4];
#pragma unroll
    for (int i = 0; i < 2; i++)
#pragma unroll
        for (int j = 0; j < 4; j++)
#pragma unroll
            for (int q = 0; q < 4; q++) acc[i][j][q] = 0.f;

#pragma unroll 1
    for (int kt = 0; kt < K_TILES; kt++) {
        cp_wait1();
        __syncthreads();

        // issue stage kt+2
        if (kt + 2 < K_TILES) {
            int s = (kt + 2) % STAGES;
            uint32_t d = sb + s * STAGE_BYTES + cp_dst;
            const uint8_t* src = cp_base + (size_t)(kt + 2) * TILE_BYTES;
#pragma unroll
            for (int j = 0; j < 4; j++) cpasync16(d + j * 16, src + j * 16);
        }
        cp_commit();

        // compute stage kt
        uint32_t sA = sb + (kt % STAGES) * STAGE_BYTES;
        uint32_t sB = sA + TILE_BYTES;
#pragma unroll
        for (int k16 = 0; k16 < 4; k16++) {
            uint32_t ka = ((uint32_t)(k16 * 32) + a_cb) ^ a_xor;
            uint32_t kb = ((uint32_t)(k16 * 32) + b_cb) ^ b_xor;
            uint32_t a0[4], a1[4], b0[4], b1[4];
            ldsm4(a0, sA + aoff0 + ka);
            ldsm4(a1, sA + aoff1 + ka);
            ldsm4(b0, sB + boff0 + kb);
            ldsm4(b1, sB + boff1 + kb);
            mma16816(acc[0][0], a0, b0 + 0);
            mma16816(acc[0][1], a0, b0 + 2);
            mma16816(acc[0][2], a0, b1 + 0);
            mma16816(acc[0][3], a0, b1 + 2);
            mma16816(acc[1][0], a1, b0 + 0);
            mma16816(acc[1][1], a1, b0 + 2);
            mma16816(acc[1][2], a1, b1 + 0);
            mma16816(acc[1][3], a1, b1 + 2);
        }
    }

    // epilogue: plain accumulator stores (scale/zero already folded into W)
    const int m_lo = mt * BM + warp_m * 32 + (lane >> 2);
    const int n_lo = nt * BN + warp_n * 32 + 2 * (lane & 3);
#pragma unroll
    for (int mtile = 0; mtile < 2; mtile++) {
        int m0 = m_lo + 16 * mtile;
        float* o0 = out + (size_t)m0 * OUT_F + n_lo;
        float* o1 = o0 + (size_t)8 * OUT_F;
#pragma unroll
        for (int j = 0; j < 4; j++) {
            float2 v0, v1;
            v0.x = acc[mtile][j][0];
            v0.y = acc[mtile][j][1];
            v1.x = acc[mtile][j][2];
            v1.y = acc[mtile][j][3];
            *(float2*)(o0 + 8 * j) = v0;
            *(float2*)(o1 + 8 * j) = v1;
        }
    }
}

// ---------------- launch ----------------
extern "C" void kernel_launch(void* const* d_in, const int* in_sizes, int n_in,
                              void* d_out, int out_size) {
    const float* x     = (const float*)d_in[0];
    const int*   wpack = (const int*)d_in[1];   // uint8 promoted to int32 by harness
    const float* scale = (const float*)d_in[2];
    const float* zero  = (const float*)d_in[3];
    float*       out   = (float*)d_out;

    cudaFuncSetAttribute(gemm_kernel, cudaFuncAttributeMaxDynamicSharedMemorySize, SMEM_BYTES);

    prep_kernel<<<X_BLOCKS + W_BLOCKS, 128>>>(x, wpack, scale, zero);
    gemm_kernel<<<M_TILES * N_TILES, 512, SMEM_BYTES>>>(out);
}

// round 15
// speedup vs baseline: 1.0194x; 1.0194x over previous
#include <cuda_runtime.h>
#include <cuda_fp16.h>
#include <cstdint>

// ---------------- problem constants ----------------
static constexpr int TOKENS = 4096;
static constexpr int IN_F   = 4096;
static constexpr int OUT_F  = 11008;

static constexpr int BM = 128;
static constexpr int BN = 128;
static constexpr int BK = 64;          // 64 fp16 = 128 bytes per row (SW128 atom row)
static constexpr int STAGES = 3;

static constexpr int M_TILES = TOKENS / BM;   // 32
static constexpr int N_TILES = OUT_F / BN;    // 86
static constexpr int K_TILES = IN_F / BK;     // 64
static constexpr int N_TILES_TOTAL = M_TILES * N_TILES; // 2752

static constexpr int TILE_BYTES = 128 * BK * 2;     // 16384 (A tile == B tile)
static constexpr int STAGE_BYTES = 2 * TILE_BYTES;  // 32768
static constexpr int SMEM_BYTES = STAGES * STAGE_BYTES + 16; // 98320 (+ tile broadcast slot)

static constexpr int X_BLOCKS = M_TILES * K_TILES;  // 2048
static constexpr int W_BLOCKS = N_TILES * K_TILES;  // 5504

static constexpr int GRID_GEMM = 296;  // 148 SMs x 2 CTAs

// ---------------- device scratch (no cudaMalloc allowed) ----------------
__device__ __align__(1024) uint8_t g_xbuf[(size_t)M_TILES * K_TILES * TILE_BYTES]; // 32 MB fp16 tiles, SW128
__device__ __align__(1024) uint8_t g_wbuf[(size_t)N_TILES * K_TILES * TILE_BYTES]; // 88 MB fp16 tiles, SW128
__device__ int g_tile_ctr;

// ---------------- helpers ----------------
__device__ __forceinline__ uint32_t smem_u32(const void* p) {
    uint32_t a;
    asm("{ .reg .u64 t; cvta.to.shared.u64 t, %1; cvt.u32.u64 %0, t; }" : "=r"(a) : "l"(p));
    return a;
}
__device__ __forceinline__ uint32_t h2u(__half2 h) { uint32_t u; __builtin_memcpy(&u, &h, 4); return u; }
__device__ __forceinline__ uint32_t swz(uint32_t off) { return off ^ ((off >> 3) & 0x70); }

__device__ __forceinline__ void cpasync16(uint32_t dst, const void* src) {
    asm volatile("cp.async.cg.shared.global [%0], [%1], 16;" :: "r"(dst), "l"(src));
}
__device__ __forceinline__ void cp_commit() { asm volatile("cp.async.commit_group;" ::: "memory"); }
__device__ __forceinline__ void cp_wait1()  { asm volatile("cp.async.wait_group 1;" ::: "memory"); }
__device__ __forceinline__ void cp_wait0()  { asm volatile("cp.async.wait_group 0;" ::: "memory"); }

__device__ __forceinline__ void ldsm4(uint32_t* r, uint32_t addr) {
    asm volatile("ldmatrix.sync.aligned.m8n8.x4.shared.b16 {%0,%1,%2,%3}, [%4];"
                 : "=r"(r[0]), "=r"(r[1]), "=r"(r[2]), "=r"(r[3]) : "r"(addr) : "memory");
}
__device__ __forceinline__ void mma16816(float* c, const uint32_t* a, const uint32_t* b) {
    asm volatile(
        "mma.sync.aligned.m16n8k16.row.col.f32.f16.f16.f32 "
        "{%0,%1,%2,%3}, {%4,%5,%6,%7}, {%8,%9}, {%0,%1,%2,%3};"
        : "+f"(c[0]), "+f"(c[1]), "+f"(c[2]), "+f"(c[3])
        : "r"(a[0]), "r"(a[1]), "r"(a[2]), "r"(a[3]), "r"(b[0]), "r"(b[1]));
}

// ---------------- merged prep kernel ----------------
__global__ void prep_kernel(const float* __restrict__ x,
                            const int* __restrict__ wp,
                            const float* __restrict__ scale,
                            const float* __restrict__ zero) {
    const int blk = blockIdx.x;
    const int r = threadIdx.x; // 0..127 = row within tile
    if (blk == 0 && r == 0) g_tile_ctr = 0;   // reset work-stealing counter each launch
    if (blk < X_BLOCKS) {
        const int mt = blk / K_TILES;
        const int kt = blk % K_TILES;
        const float4* src = (const float4*)(x + (size_t)(mt * BM + r) * IN_F + kt * BK);
        uint8_t* dst = g_xbuf + (size_t)blk * TILE_BYTES;
#pragma unroll
        for (int g = 0; g < 8; g++) {
            float4 a = src[2 * g];
            float4 b = src[2 * g + 1];
            uint4 v;
            v.x = h2u(__floats2half2_rn(a.x, a.y));
            v.y = h2u(__floats2half2_rn(a.z, a.w));
            v.z = h2u(__floats2half2_rn(b.x, b.y));
            v.w = h2u(__floats2half2_rn(b.z, b.w));
            uint32_t off = (uint32_t)(r * 128 + g * 16);
            *(uint4*)(dst + swz(off)) = v;
        }
    } else {
        const int wblk = blk - X_BLOCKS;
        const int nt = wblk / K_TILES;
        const int kt = wblk % K_TILES;
        const int row = nt * BN + r;
        const float s = scale[row];
        const float b = -zero[row] * s;
        const uint4* src = (const uint4*)(wp + (size_t)row * (IN_F / 2) + kt * (BK / 2)); // 32 ints
        uint8_t* dst = g_wbuf + (size_t)wblk * TILE_BYTES;
#pragma unroll
        for (int j = 0; j < 8; j++) {
            uint4 q = src[j];
            uint32_t e[4] = {q.x, q.y, q.z, q.w};
            uint32_t h[4];
#pragma unroll
            for (int t = 0; t < 4; t++) {
                float v0 = fmaf((float)(e[t] & 15u), s, b);          // even k
                float v1 = fmaf((float)((e[t] >> 4) & 15u), s, b);   // odd k
                h[t] = h2u(__floats2half2_rn(v0, v1));
            }
            uint4 v = make_uint4(h[0], h[1], h[2], h[3]);
            uint32_t off = (uint32_t)(r * 128 + j * 16);
            *(uint4*)(dst + swz(off)) = v;
        }
    }
}

// ---------------- persistent GEMM: dynamic tile stealing, R12 mainloop ----------------
// 256 threads = 8 warps in a 4(M) x 2(N) grid; warp tile 32x64; 2 CTAs/SM; grid = 296.
__global__ void __launch_bounds__(256, 2) gemm_kernel(float* __restrict__ out) {
    extern __shared__ __align__(1024) uint8_t sm[];
    uint32_t sb = smem_u32(sm);
    volatile int* s_tile = (volatile int*)(sm + STAGES * STAGE_BYTES);
    const int tid  = threadIdx.x;
    const int lane = tid & 31;
    const int warp = tid >> 5;
    const int warp_m = warp & 3;
    const int warp_n = warp >> 2;

    const uint32_t cp_off = (uint32_t)tid * 64;

    // per-lane ldmatrix address components (SW128: swz(r*128+c) = r*128 + (c ^ ((r&7)<<4)))
    const int a_row = warp_m * 32 + (lane & 15);          // + 16*mtile
    const uint32_t a_xor = (uint32_t)((a_row & 7) << 4);
    const uint32_t a_cb  = (uint32_t)((lane >> 4) << 4);  // 0 or 16
    const int b_row = warp_n * 64 + (lane & 7) + ((lane >> 4) << 3);  // + 16*p
    const uint32_t b_xor = (uint32_t)((b_row & 7) << 4);
    const uint32_t b_cb  = (uint32_t)((lane & 8) << 1);   // 0 or 16

    const uint32_t aoff0 = (uint32_t)(a_row +  0) * 128;
    const uint32_t aoff1 = (uint32_t)(a_row + 16) * 128;
    uint32_t boff[4];
#pragma unroll
    for (int p = 0; p < 4; p++) boff[p] = (uint32_t)(b_row + 16 * p) * 128;

    uint32_t bfr[2][16];   // [k16 parity][4 groups x 4 regs]
    uint32_t afr[2][4];    // current k16 A, 2 mtiles

    while (true) {
        if (tid == 0) s_tile[0] = atomicAdd(&g_tile_ctr, 1);
        __syncthreads();                    // broadcast + all warps done with prior tile's smem
        const int tile = s_tile[0];
        if (tile >= N_TILES_TOTAL) break;
        const int mt = tile % M_TILES;
        const int nt = tile / M_TILES;

        const uint8_t* ag = g_xbuf + (size_t)(mt * K_TILES) * TILE_BYTES;
        const uint8_t* bg = g_wbuf + (size_t)(nt * K_TILES) * TILE_BYTES;

        cp_wait0();                         // drain any stale groups before rewriting stages

        // prologue: stages 0 and 1
#pragma unroll
        for (int s = 0; s < 2; s++) {
            uint32_t dA = sb + s * STAGE_BYTES + cp_off;
            uint32_t dB = dA + TILE_BYTES;
            const uint8_t* srcA = ag + (size_t)s * TILE_BYTES + cp_off;
            const uint8_t* srcB = bg + (size_t)s * TILE_BYTES + cp_off;
#pragma unroll
            for (int j = 0; j < 4; j++) {
                cpasync16(dA + j * 16, srcA + j * 16);
                cpasync16(dB + j * 16, srcB + j * 16);
            }
            cp_commit();
        }

        float acc[2][8][4];
#pragma unroll
        for (int i = 0; i < 2; i++)
#pragma unroll
            for (int j = 0; j < 8; j++)
#pragma unroll
                for (int q = 0; q < 4; q++) acc[i][j][q] = 0.f;

#pragma unroll 1
        for (int kt = 0; kt < K_TILES; kt++) {
            cp_wait1();
            __syncthreads();

            // issue stage kt+2
            if (kt + 2 < K_TILES) {
                int s = (kt + 2) % STAGES;
                uint32_t dA = sb + s * STAGE_BYTES + cp_off;
                uint32_t dB = dA + TILE_BYTES;
                const uint8_t* srcA = ag + (size_t)(kt + 2) * TILE_BYTES + cp_off;
                const uint8_t* srcB = bg + (size_t)(kt + 2) * TILE_BYTES + cp_off;
#pragma unroll
                for (int j = 0; j < 4; j++) {
                    cpasync16(dA + j * 16, srcA + j * 16);
                    cpasync16(dB + j * 16, srcB + j * 16);
                }
            }
            cp_commit();

            // compute stage kt
            uint32_t sA = sb + (kt % STAGES) * STAGE_BYTES;
            uint32_t sB = sA + TILE_BYTES;

            // prime B for k16=0
            {
                uint32_t kx = b_cb ^ b_xor;
#pragma unroll
                for (int p = 0; p < 4; p++) ldsm4(&bfr[0][4 * p], sB + boff[p] + kx);
            }

#pragma unroll
            for (int k16 = 0; k16 < 4; k16++) {
                uint32_t ka = ((uint32_t)(k16 * 32) + a_cb) ^ a_xor;
                ldsm4(afr[0], sA + aoff0 + ka);
                ldsm4(afr[1], sA + aoff1 + ka);
                if (k16 < 3) {
                    uint32_t kx = ((uint32_t)((k16 + 1) * 32) + b_cb) ^ b_xor;
#pragma unroll
                    for (int p = 0; p < 4; p++) ldsm4(&bfr[(k16 + 1) & 1][4 * p], sB + boff[p] + kx);
                }
#pragma unroll
                for (int p = 0; p < 4; p++) {
                    const uint32_t* bb = &bfr[k16 & 1][4 * p];
                    mma16816(acc[0][2 * p + 0], afr[0], bb + 0);
                    mma16816(acc[0][2 * p + 1], afr[0], bb + 2);
                    mma16816(acc[1][2 * p + 0], afr[1], bb + 0);
                    mma16816(acc[1][2 * p + 1], afr[1], bb + 2);
                }
            }
        }

        // epilogue: plain accumulator stores (scale/zero already folded into W)
        const int m_lo = mt * BM + warp_m * 32 + (lane >> 2);
        const int n_lo = nt * BN + warp_n * 64 + 2 * (lane & 3);
#pragma unroll
        for (int mtile = 0; mtile < 2; mtile++) {
            int m0 = m_lo + 16 * mtile;
            float* o0 = out + (size_t)m0 * OUT_F + n_lo;
            float* o1 = o0 + (size_t)8 * OUT_F;
#pragma unroll
            for (int p = 0; p < 8; p++) {
                float2 v0, v1;
                v0.x = acc[mtile][p][0];
                v0.y = acc[mtile][p][1];
                v1.x = acc[mtile][p][2];
                v1.y = acc[mtile][p][3];
                *(float2*)(o0 + 8 * p) = v0;
                *(float2*)(o1 + 8 * p) = v1;
            }
        }
    }
}

// ---------------- launch ----------------
extern "C" void kernel_launch(void* const* d_in, const int* in_sizes, int n_in,
                              void* d_out, int out_size) {
    const float* x     = (const float*)d_in[0];
    const int*   wpack = (const int*)d_in[1];   // uint8 promoted to int32 by harness
    const float* scale = (const float*)d_in[2];
    const float* zero  = (const float*)d_in[3];
    float*       out   = (float*)d_out;

    cudaFuncSetAttribute(gemm_kernel, cudaFuncAttributeMaxDynamicSharedMemorySize, SMEM_BYTES);

    prep_kernel<<<X_BLOCKS + W_BLOCKS, 128>>>(x, wpack, scale, zero);
    gemm_kernel<<<GRID_GEMM, 256, SMEM_BYTES>>>(out);
}